// round 1
// baseline (speedup 1.0000x reference)
#include <cuda_runtime.h>
#include <cstdint>
#include <math.h>

// Shapes (fixed for this problem)
#define BB 32
#define TT 4
#define LL 196
#define DD 512
#define HH 8
#define ROWS (BB*TT*LL)          // 25088
#define GK DD                    // 512
#define GN DD                    // 512

// Scratch (device globals -- no runtime allocation allowed)
__device__ float g_Y[(size_t)ROWS * DD];    // GEMM output / attention output reuse
__device__ float g_S2[(size_t)ROWS * DD];   // attn-LIF spikes (0/1 fp32)
__device__ unsigned long long g_qb[TT*BB*HH*LL];
__device__ unsigned long long g_kb[TT*BB*HH*LL];
__device__ unsigned long long g_vb[TT*BB*HH*LL];

// ---------------------------------------------------------------------------
// Dense fp32 GEMM: C[m,n] = sum_k A[m,k]*W[n,k] + bias[n]
// A: [ROWS, 512] row-major; W: [512, 512] row-major (out, in). 128x128x8 tile.
// ---------------------------------------------------------------------------
__global__ void __launch_bounds__(256, 2) sgemm_kernel(
    const float* __restrict__ A, const float* __restrict__ W,
    const float* __restrict__ bias, float* __restrict__ C)
{
    __shared__ float As[8][128];
    __shared__ float Bs[8][128];
    const int tid  = threadIdx.x;
    const int bn   = blockIdx.x * 128;
    const int bm   = blockIdx.y * 128;
    const int lrow = tid >> 1;
    const int lcol = (tid & 1) << 2;
    const float* Ag = A + (size_t)(bm + lrow) * GK + lcol;
    const float* Wg = W + (size_t)(bn + lrow) * GK + lcol;
    const int tx = (tid & 15) << 2;   // 0..60
    const int ty = (tid >> 4) << 2;   // 0..60

    float acc[8][8];
#pragma unroll
    for (int i = 0; i < 8; i++)
#pragma unroll
        for (int j = 0; j < 8; j++) acc[i][j] = 0.f;

    for (int k0 = 0; k0 < GK; k0 += 8) {
        float4 a4 = *(const float4*)(Ag + k0);
        float4 w4 = *(const float4*)(Wg + k0);
        As[lcol + 0][lrow] = a4.x; As[lcol + 1][lrow] = a4.y;
        As[lcol + 2][lrow] = a4.z; As[lcol + 3][lrow] = a4.w;
        Bs[lcol + 0][lrow] = w4.x; Bs[lcol + 1][lrow] = w4.y;
        Bs[lcol + 2][lrow] = w4.z; Bs[lcol + 3][lrow] = w4.w;
        __syncthreads();
#pragma unroll
        for (int kk = 0; kk < 8; kk++) {
            float a[8], b[8];
            *(float4*)&a[0] = *(const float4*)&As[kk][ty];
            *(float4*)&a[4] = *(const float4*)&As[kk][ty + 64];
            *(float4*)&b[0] = *(const float4*)&Bs[kk][tx];
            *(float4*)&b[4] = *(const float4*)&Bs[kk][tx + 64];
#pragma unroll
            for (int i = 0; i < 8; i++)
#pragma unroll
                for (int j = 0; j < 8; j++)
                    acc[i][j] += a[i] * b[j];
        }
        __syncthreads();
    }

#pragma unroll
    for (int i = 0; i < 8; i++) {
        int m = bm + ((i < 4) ? (ty + i) : (64 + ty + i - 4));
#pragma unroll
        for (int j = 0; j < 8; j++) {
            int n = bn + ((j < 4) ? (tx + j) : (64 + tx + j - 4));
            C[(size_t)m * GN + n] = acc[i][j] + bias[n];
        }
    }
}

// ---------------------------------------------------------------------------
// Fused LayerNorm (per t-row) + LIF scan over T + spike emission.
// One block per (b,l). Warp w owns head w: channels cA=w*64+lane, cB=cA+32.
// If bits != nullptr: pack spikes per (t,b,h,l) as uint64 (bit c-of-head).
// Else: write fp32 0/1 spikes to outf at [b,t,l,c].
// ---------------------------------------------------------------------------
__global__ void __launch_bounds__(256) ln_lif_kernel(
    const float* __restrict__ Y, const float* __restrict__ g,
    const float* __restrict__ be, float thr,
    unsigned long long* __restrict__ bits, float* __restrict__ outf)
{
    const int bl = blockIdx.x;
    const int b = bl / LL, l = bl % LL;
    const int tid = threadIdx.x, w = tid >> 5, lane = tid & 31;
    const int cA = w * 64 + lane, cB = cA + 32;
    __shared__ float red[8];
    const float gA = g[cA], gB = g[cB], beA = be[cA], beB = be[cB];
    float vA = 0.f, vB = 0.f;

    for (int t = 0; t < TT; t++) {
        const size_t roff = ((size_t)((b * TT + t) * LL + l)) * DD;
        const float yA = Y[roff + cA], yB = Y[roff + cB];

        // mean
        float s = yA + yB;
#pragma unroll
        for (int o = 16; o; o >>= 1) s += __shfl_xor_sync(0xffffffffu, s, o);
        if (lane == 0) red[w] = s;
        __syncthreads();
        float S = 0.f;
#pragma unroll
        for (int i = 0; i < 8; i++) S += red[i];
        const float mean = S * (1.f / 512.f);
        __syncthreads();

        // variance (two-pass, matching jnp.var)
        const float dA = yA - mean, dB = yB - mean;
        float q = dA * dA + dB * dB;
#pragma unroll
        for (int o = 16; o; o >>= 1) q += __shfl_xor_sync(0xffffffffu, q, o);
        if (lane == 0) red[w] = q;
        __syncthreads();
        float Q = 0.f;
#pragma unroll
        for (int i = 0; i < 8; i++) Q += red[i];
        __syncthreads();
        const float var = Q * (1.f / 512.f);
        const float rstd = (float)(1.0 / sqrt((double)var + 1e-5));

        const float nA = dA * rstd * gA + beA;
        const float nB = dB * rstd * gB + beB;

        // LIF: v = (v + x)/2 ; spike = (v >= thr) ; hard reset
        vA = (vA + nA) * 0.5f;
        vB = (vB + nB) * 0.5f;
        const bool sA = (vA >= thr), sB = (vB >= thr);
        if (sA) vA = 0.f;
        if (sB) vB = 0.f;

        if (bits) {
            unsigned mA = __ballot_sync(0xffffffffu, sA);
            unsigned mB = __ballot_sync(0xffffffffu, sB);
            if (lane == 0)
                bits[((size_t)(t * BB + b) * HH + w) * LL + l] =
                    (unsigned long long)mA | ((unsigned long long)mB << 32);
        } else {
            outf[roff + cA] = sA ? 1.f : 0.f;
            outf[roff + cB] = sB ? 1.f : 0.f;
        }
    }
}

// ---------------------------------------------------------------------------
// Binary attention: o[l,c] = 0.25 * sum_j popcount(q_l & k_j) * v_bit(j,c)
// One block per (t,b,h). k,v bitmasks staged in smem. Warp processes 4 l-rows
// at a time; lane owns channels (lane, lane+32) of the 64-wide head.
// Writes O (scaled) into [b,t,l, h*64+c] layout.
// ---------------------------------------------------------------------------
__global__ void __launch_bounds__(256) attn_kernel(
    const unsigned long long* __restrict__ qb,
    const unsigned long long* __restrict__ kb,
    const unsigned long long* __restrict__ vb,
    float* __restrict__ O)
{
    __shared__ unsigned long long ks[LL], vs[LL];
    const int blk = blockIdx.x;              // t*256 + b*8 + h
    const int t = blk >> 8;
    const int b = (blk >> 3) & 31;
    const int h = blk & 7;
    const size_t base = ((size_t)(t * BB + b) * HH + h) * LL;
    const int tid = threadIdx.x;
    if (tid < LL) { ks[tid] = kb[base + tid]; vs[tid] = vb[base + tid]; }
    __syncthreads();

    const int w = tid >> 5, lane = tid & 31;
    for (int l0 = w * 4; l0 < LL; l0 += 32) {
        const unsigned long long q0 = qb[base + l0 + 0];
        const unsigned long long q1 = qb[base + l0 + 1];
        const unsigned long long q2 = qb[base + l0 + 2];
        const unsigned long long q3 = qb[base + l0 + 3];
        int a00 = 0, a01 = 0, a10 = 0, a11 = 0;
        int a20 = 0, a21 = 0, a30 = 0, a31 = 0;
        for (int j = 0; j < LL; j++) {
            const unsigned long long kj = ks[j];
            const unsigned long long vj = vs[j];
            const int b0 = (int)((vj >> lane) & 1ull);
            const int b1 = (int)((vj >> (lane + 32)) & 1ull);
            const int w0 = __popcll(q0 & kj);
            const int w1 = __popcll(q1 & kj);
            const int w2 = __popcll(q2 & kj);
            const int w3 = __popcll(q3 & kj);
            a00 += b0 * w0; a01 += b1 * w0;
            a10 += b0 * w1; a11 += b1 * w1;
            a20 += b0 * w2; a21 += b1 * w2;
            a30 += b0 * w3; a31 += b1 * w3;
        }
        const int cb = h * 64 + lane;
        const size_t r0 = ((size_t)((b * TT + t) * LL + l0)) * DD;
        O[r0 +            cb] = a00 * 0.25f;  O[r0 +            cb + 32] = a01 * 0.25f;
        O[r0 +  512 +     cb] = a10 * 0.25f;  O[r0 +  512 +     cb + 32] = a11 * 0.25f;
        O[r0 + 1024 +     cb] = a20 * 0.25f;  O[r0 + 1024 +     cb + 32] = a21 * 0.25f;
        O[r0 + 1536 +     cb] = a30 * 0.25f;  O[r0 + 1536 +     cb + 32] = a31 * 0.25f;
    }
}

// ---------------------------------------------------------------------------
// LIF (thr = 0.5) on attention output, no LN. Writes fp32 0/1 spikes.
// Thread per (b,l,c), scans T=4. All arithmetic exact (dyadic rationals).
// ---------------------------------------------------------------------------
__global__ void __launch_bounds__(256) lif_attn_kernel(
    const float* __restrict__ O, float* __restrict__ S2)
{
    const int idx = blockIdx.x * 256 + threadIdx.x;
    if (idx >= BB * LL * DD) return;
    const int c = idx & 511;
    const int bl = idx >> 9;
    const int b = bl / LL, l = bl % LL;
    float v = 0.f;
#pragma unroll
    for (int t = 0; t < TT; t++) {
        const size_t off = ((size_t)((b * TT + t) * LL + l)) * DD + c;
        const float x = O[off];
        v = (v + x) * 0.5f;
        const bool s = (v >= 0.5f);
        S2[off] = s ? 1.f : 0.f;
        if (s) v = 0.f;
    }
}

// ---------------------------------------------------------------------------
extern "C" void kernel_launch(void* const* d_in, const int* in_sizes, int n_in,
                              void* d_out, int out_size)
{
    const float* x   = (const float*)d_in[0];
    const float* Wq  = (const float*)d_in[1];
    const float* bq  = (const float*)d_in[2];
    const float* gq  = (const float*)d_in[3];
    const float* beq = (const float*)d_in[4];
    const float* Wk  = (const float*)d_in[5];
    const float* bk  = (const float*)d_in[6];
    const float* gk  = (const float*)d_in[7];
    const float* bek = (const float*)d_in[8];
    const float* Wv  = (const float*)d_in[9];
    const float* bv  = (const float*)d_in[10];
    const float* gv  = (const float*)d_in[11];
    const float* bev = (const float*)d_in[12];
    const float* Wl  = (const float*)d_in[13];
    const float* bl_ = (const float*)d_in[14];
    const float* gl  = (const float*)d_in[15];
    const float* bel = (const float*)d_in[16];
    float* out = (float*)d_out;

    float *Y, *S2;
    unsigned long long *qb, *kb, *vb;
    cudaGetSymbolAddress((void**)&Y,  g_Y);
    cudaGetSymbolAddress((void**)&S2, g_S2);
    cudaGetSymbolAddress((void**)&qb, g_qb);
    cudaGetSymbolAddress((void**)&kb, g_kb);
    cudaGetSymbolAddress((void**)&vb, g_vb);

    const dim3 ggrid(GN / 128, ROWS / 128);   // (4, 196)
    const int nBL = BB * LL;                  // 6272

    // Q branch
    sgemm_kernel<<<ggrid, 256>>>(x, Wq, bq, Y);
    ln_lif_kernel<<<nBL, 256>>>(Y, gq, beq, 1.0f, qb, nullptr);
    // K branch
    sgemm_kernel<<<ggrid, 256>>>(x, Wk, bk, Y);
    ln_lif_kernel<<<nBL, 256>>>(Y, gk, bek, 1.0f, kb, nullptr);
    // V branch
    sgemm_kernel<<<ggrid, 256>>>(x, Wv, bv, Y);
    ln_lif_kernel<<<nBL, 256>>>(Y, gv, bev, 1.0f, vb, nullptr);

    // Binary attention (exact integer math), output scaled by 0.25
    attn_kernel<<<TT * BB * HH, 256>>>(qb, kb, vb, Y);

    // attn-LIF (thr = 0.5), exact
    lif_attn_kernel<<<(BB * LL * DD + 255) / 256, 256>>>(Y, S2);

    // Final projection + LN + LIF -> output [B,T,L,D]
    sgemm_kernel<<<ggrid, 256>>>(S2, Wl, bl_, Y);
    ln_lif_kernel<<<nBL, 256>>>(Y, gl, bel, 1.0f, nullptr, out);
}